// round 1
// baseline (speedup 1.0000x reference)
#include <cuda_runtime.h>

#define NN 50000
#define EE 800000
#define FIN 128
#define HH 100
#define CC 16

// Scratch (no allocations allowed) — ~43MB of device globals.
__device__ float g_deg[NN];
__device__ float g_dinv[NN];
__device__ float g_h1[NN * HH];   // x @ W1
__device__ float g_h1p[NN * HH];  // propagated layer-1
__device__ float g_h2[NN * CC];   // a1 @ W2
__device__ float g_h2p[NN * CC];  // propagated layer-2

__device__ __forceinline__ void red4(float* p, float x, float y, float z, float w) {
    asm volatile("red.global.add.v4.f32 [%0], {%1,%2,%3,%4};"
                 :: "l"(p), "f"(x), "f"(y), "f"(z), "f"(w)
                 : "memory");
}

// ---------------- degree / norm ----------------

__global__ void k_deg_init() {
    int i = blockIdx.x * blockDim.x + threadIdx.x;
    if (i < NN) g_deg[i] = 1.0f;  // self-loop
}

__global__ void k_deg_count(const int* __restrict__ dst) {
    int e = blockIdx.x * blockDim.x + threadIdx.x;
    if (e < EE) atomicAdd(&g_deg[dst[e]], 1.0f);
}

__global__ void k_dinv() {
    int i = blockIdx.x * blockDim.x + threadIdx.x;
    if (i < NN) g_dinv[i] = rsqrtf(g_deg[i]);  // deg >= 1 always (self-loop)
}

// ---------------- GEMM1: h1 = x @ W1  (50000x128 @ 128x100) ----------------
// 64-row tile, N padded to 128 in the tile, 256 threads, 4x8 register tile.

__global__ __launch_bounds__(256) void k_gemm1(const float* __restrict__ x,
                                               const float* __restrict__ W1) {
    __shared__ float As[64][36];   // pad to 36 -> bank-shift rows, keeps 16B align
    __shared__ float Bs[32][128];

    const int m0  = blockIdx.x * 64;
    const int tid = threadIdx.x;
    const int tx  = tid & 15;      // col group
    const int ty  = tid >> 4;      // row group

    float acc[4][8];
#pragma unroll
    for (int i = 0; i < 4; i++)
#pragma unroll
        for (int j = 0; j < 8; j++) acc[i][j] = 0.0f;

#pragma unroll
    for (int k0 = 0; k0 < FIN; k0 += 32) {
        // load A tile: 64 rows x 32 k (float4 per thread x2)
        {
            int row = tid >> 3;            // 0..31
            int kk  = (tid & 7) << 2;      // 0,4,...,28
#pragma unroll
            for (int rr = 0; rr < 64; rr += 32) {
                int gr = m0 + row + rr;
                float4 v = make_float4(0.f, 0.f, 0.f, 0.f);
                if (gr < NN) v = *(const float4*)&x[gr * FIN + k0 + kk];
                *(float4*)&As[row + rr][kk] = v;
            }
        }
        // load B tile: 32 k x 128 cols (cols >= 100 zero-padded)
#pragma unroll
        for (int i = 0; i < 16; i++) {
            int idx = tid + i * 256;
            int k = idx >> 7, c = idx & 127;
            Bs[k][c] = (c < HH) ? W1[(k0 + k) * HH + c] : 0.0f;
        }
        __syncthreads();

#pragma unroll
        for (int k = 0; k < 32; k++) {
            float a[4], b[8];
#pragma unroll
            for (int i = 0; i < 4; i++) a[i] = As[ty + 16 * i][k];
#pragma unroll
            for (int j = 0; j < 8; j++) b[j] = Bs[k][tx + 16 * j];
#pragma unroll
            for (int i = 0; i < 4; i++)
#pragma unroll
                for (int j = 0; j < 8; j++) acc[i][j] += a[i] * b[j];
        }
        __syncthreads();
    }

#pragma unroll
    for (int i = 0; i < 4; i++) {
        int r = m0 + ty + 16 * i;
        if (r < NN) {
#pragma unroll
            for (int j = 0; j < 8; j++) {
                int c = tx + 16 * j;
                if (c < HH) g_h1[r * HH + c] = acc[i][j];
            }
        }
    }
}

// ---------------- propagation layer 1 ----------------
// self-loop init: h1p[i][:] = h1[i][:] / deg[i]   (dinv[i]^2 == 1/deg[i])
__global__ void k_self1() {
    int t = blockIdx.x * blockDim.x + threadIdx.x;  // one float4 each
    if (t >= NN * (HH / 4)) return;
    int row = t / (HH / 4);
    float inv = 1.0f / g_deg[row];
    float4 v = *(const float4*)&g_h1[t * 4];
    float4 o = make_float4(v.x * inv, v.y * inv, v.z * inv, v.w * inv);
    *(float4*)&g_h1p[t * 4] = o;
}

// edge scatter: warp per edge, 25 float4 lanes
__global__ __launch_bounds__(256) void k_prop1(const int* __restrict__ src,
                                               const int* __restrict__ dst) {
    int w = (blockIdx.x * blockDim.x + threadIdx.x) >> 5;
    int lane = threadIdx.x & 31;
    if (w >= EE) return;
    int s = src[w];
    int d = dst[w];
    float c = g_dinv[s] * g_dinv[d];
    if (lane < HH / 4) {
        const float4 v = *(const float4*)&g_h1[s * HH + (lane << 2)];
        red4(&g_h1p[d * HH + (lane << 2)], v.x * c, v.y * c, v.z * c, v.w * c);
    }
}

// ---------------- GEMM2: h2 = leaky(h1p + b1) @ W2  (50000x100 @ 100x16) ----
__global__ __launch_bounds__(256) void k_gemm2(const float* __restrict__ b1,
                                               const float* __restrict__ W2) {
    __shared__ float w2s[HH * CC];     // 100x16
    __shared__ float a1s[16][HH];      // 16 rows
    int tid = threadIdx.x;
    int r0  = blockIdx.x * 16;

    for (int i = tid; i < HH * CC; i += 256) w2s[i] = W2[i];
    for (int i = tid; i < 16 * HH; i += 256) {
        int r = i / HH, c = i % HH;
        int gr = r0 + r;
        float v = 0.0f;
        if (gr < NN) {
            v = g_h1p[gr * HH + c] + b1[c];
            v = (v > 0.0f) ? v : 0.01f * v;   // leaky relu
        }
        a1s[r][c] = v;
    }
    __syncthreads();

    int r = tid >> 4;       // 0..15
    int c = tid & 15;       // 0..15
    float acc = 0.0f;
#pragma unroll
    for (int k = 0; k < HH; k++) acc += a1s[r][k] * w2s[k * CC + c];
    int gr = r0 + r;
    if (gr < NN) g_h2[gr * CC + c] = acc;
}

// ---------------- propagation layer 2 ----------------
__global__ void k_self2() {
    int t = blockIdx.x * blockDim.x + threadIdx.x;  // one float4 each
    if (t >= NN * (CC / 4)) return;
    int row = t >> 2;
    float inv = 1.0f / g_deg[row];
    float4 v = *(const float4*)&g_h2[t * 4];
    float4 o = make_float4(v.x * inv, v.y * inv, v.z * inv, v.w * inv);
    *(float4*)&g_h2p[t * 4] = o;
}

__global__ __launch_bounds__(256) void k_prop2(const int* __restrict__ src,
                                               const int* __restrict__ dst) {
    int gid = blockIdx.x * blockDim.x + threadIdx.x;
    int e = gid >> 2;
    if (e >= EE) return;
    int q = gid & 3;
    int s = src[e];
    int d = dst[e];
    float c = g_dinv[s] * g_dinv[d];
    const float4 v = *(const float4*)&g_h2[s * CC + (q << 2)];
    red4(&g_h2p[d * CC + (q << 2)], v.x * c, v.y * c, v.z * c, v.w * c);
}

// ---------------- bias + log_softmax ----------------
__global__ void k_final(const float* __restrict__ b2, float* __restrict__ out) {
    int i = blockIdx.x * blockDim.x + threadIdx.x;
    if (i >= NN) return;
    float v[CC];
#pragma unroll
    for (int q = 0; q < 4; q++) {
        float4 t = *(const float4*)&g_h2p[i * CC + (q << 2)];
        v[4 * q + 0] = t.x; v[4 * q + 1] = t.y;
        v[4 * q + 2] = t.z; v[4 * q + 3] = t.w;
    }
#pragma unroll
    for (int k = 0; k < CC; k++) v[k] += b2[k];
    float m = v[0];
#pragma unroll
    for (int k = 1; k < CC; k++) m = fmaxf(m, v[k]);
    float s = 0.0f;
#pragma unroll
    for (int k = 0; k < CC; k++) s += expf(v[k] - m);
    float ls = logf(s) + m;
#pragma unroll
    for (int q = 0; q < 4; q++) {
        float4 t = make_float4(v[4 * q + 0] - ls, v[4 * q + 1] - ls,
                               v[4 * q + 2] - ls, v[4 * q + 3] - ls);
        *(float4*)&out[i * CC + (q << 2)] = t;
    }
}

// ---------------- launcher ----------------
extern "C" void kernel_launch(void* const* d_in, const int* in_sizes, int n_in,
                              void* d_out, int out_size) {
    const float* x  = (const float*)d_in[0];
    const float* W1 = (const float*)d_in[1];
    const float* b1 = (const float*)d_in[2];
    const float* W2 = (const float*)d_in[3];
    const float* b2 = (const float*)d_in[4];
    const int*   ei = (const int*)d_in[5];
    const int* src = ei;        // edge_index[0]
    const int* dst = ei + EE;   // edge_index[1]
    float* out = (float*)d_out;

    k_deg_init<<<(NN + 255) / 256, 256>>>();
    k_deg_count<<<(EE + 255) / 256, 256>>>(dst);
    k_dinv<<<(NN + 255) / 256, 256>>>();

    k_gemm1<<<(NN + 63) / 64, 256>>>(x, W1);
    k_self1<<<(NN * (HH / 4) + 255) / 256, 256>>>();
    k_prop1<<<(EE * 32) / 256, 256>>>(src, dst);

    k_gemm2<<<(NN + 15) / 16, 256>>>(b1, W2);
    k_self2<<<(NN * (CC / 4) + 255) / 256, 256>>>();
    k_prop2<<<(EE * 4 + 255) / 256, 256>>>(src, dst);

    k_final<<<(NN + 255) / 256, 256>>>(b2, out);
}

// round 3
// speedup vs baseline: 1.2265x; 1.2265x over previous
#include <cuda_runtime.h>

#define NN 50000
#define EE 800000
#define FIN 128
#define HH 100
#define CC 16
#define SCAN_B 512
#define NCHUNK ((NN + SCAN_B - 1) / SCAN_B)   // 98

// ---- scratch (device globals; no allocations) ----
__device__ float g_dinv[NN];
__device__ int   g_cnt[NN];
__device__ int   g_incl[NN];          // inclusive scan within chunk
__device__ int   g_bsum[NCHUNK];
__device__ int   g_boff[NCHUNK];
__device__ int   g_rowptr[NN + 1];
__device__ int   g_cur[NN];
__device__ int   g_csr_src[EE];
__device__ float g_csr_w[EE];
__device__ float g_h1[NN * HH];       // x @ W1
__device__ float g_h1p[NN * HH];      // propagated layer-1
__device__ float g_h2[NN * CC];       // a1 @ W2

// ================= CSR build =================

__global__ void k_zero() {
    int i = blockIdx.x * blockDim.x + threadIdx.x;
    if (i < NN) g_cnt[i] = 0;
}

__global__ void k_count(const int* __restrict__ dst) {
    int e = blockIdx.x * blockDim.x + threadIdx.x;
    if (e < EE) atomicAdd(&g_cnt[dst[e]], 1);
}

__global__ __launch_bounds__(SCAN_B) void k_scan1() {
    __shared__ int sh[SCAN_B];
    int t = threadIdx.x;
    int i = blockIdx.x * SCAN_B + t;
    int v = (i < NN) ? g_cnt[i] : 0;
    sh[t] = v;
    __syncthreads();
#pragma unroll
    for (int off = 1; off < SCAN_B; off <<= 1) {
        int a = (t >= off) ? sh[t - off] : 0;
        __syncthreads();
        sh[t] += a;
        __syncthreads();
    }
    if (i < NN) g_incl[i] = sh[t];
    if (t == SCAN_B - 1) g_bsum[blockIdx.x] = sh[t];
}

__global__ void k_scan2() {
    if (threadIdx.x == 0) {
        int run = 0;
        for (int b = 0; b < NCHUNK; b++) {
            g_boff[b] = run;
            run += g_bsum[b];
        }
    }
}

__global__ __launch_bounds__(SCAN_B) void k_scan3() {
    int i = blockIdx.x * SCAN_B + threadIdx.x;
    if (i < NN) {
        int cnt = g_cnt[i];
        int excl = g_incl[i] - cnt + g_boff[blockIdx.x];
        g_rowptr[i] = excl;
        g_cur[i] = excl;
        g_dinv[i] = rsqrtf((float)(cnt + 1));  // +1 self loop
    }
    if (i == 0) g_rowptr[NN] = EE;
}

__global__ void k_scatter(const int* __restrict__ src, const int* __restrict__ dst) {
    int e = blockIdx.x * blockDim.x + threadIdx.x;
    if (e >= EE) return;
    int s = src[e], d = dst[e];
    int pos = atomicAdd(&g_cur[d], 1);
    g_csr_src[pos] = s;
    g_csr_w[pos] = g_dinv[s] * g_dinv[d];
}

// ================ GEMM1: h1 = x @ W1 (50000x128 @ 128x100) ================

__global__ __launch_bounds__(256) void k_gemm1(const float* __restrict__ x,
                                               const float* __restrict__ W1) {
    __shared__ float As[64][36];
    __shared__ float Bs[32][128];

    const int m0  = blockIdx.x * 64;
    const int tid = threadIdx.x;
    const int tx  = tid & 15;
    const int ty  = tid >> 4;

    float acc[4][8];
#pragma unroll
    for (int i = 0; i < 4; i++)
#pragma unroll
        for (int j = 0; j < 8; j++) acc[i][j] = 0.0f;

#pragma unroll
    for (int k0 = 0; k0 < FIN; k0 += 32) {
        {
            int row = tid >> 3;
            int kk  = (tid & 7) << 2;
#pragma unroll
            for (int rr = 0; rr < 64; rr += 32) {
                int gr = m0 + row + rr;
                float4 v = make_float4(0.f, 0.f, 0.f, 0.f);
                if (gr < NN) v = *(const float4*)&x[gr * FIN + k0 + kk];
                *(float4*)&As[row + rr][kk] = v;
            }
        }
#pragma unroll
        for (int i = 0; i < 16; i++) {
            int idx = tid + i * 256;
            int k = idx >> 7, c = idx & 127;
            Bs[k][c] = (c < HH) ? W1[(k0 + k) * HH + c] : 0.0f;
        }
        __syncthreads();

#pragma unroll
        for (int k = 0; k < 32; k++) {
            float a[4], b[8];
#pragma unroll
            for (int i = 0; i < 4; i++) a[i] = As[ty + 16 * i][k];
#pragma unroll
            for (int j = 0; j < 8; j++) b[j] = Bs[k][tx + 16 * j];
#pragma unroll
            for (int i = 0; i < 4; i++)
#pragma unroll
                for (int j = 0; j < 8; j++) acc[i][j] += a[i] * b[j];
        }
        __syncthreads();
    }

#pragma unroll
    for (int i = 0; i < 4; i++) {
        int r = m0 + ty + 16 * i;
        if (r < NN) {
#pragma unroll
            for (int j = 0; j < 8; j++) {
                int c = tx + 16 * j;
                if (c < HH) g_h1[r * HH + c] = acc[i][j];
            }
        }
    }
}

// ============ prop1: gather per destination node (warp/node) ============

__global__ __launch_bounds__(256) void k_prop1() {
    int w = (blockIdx.x * blockDim.x + threadIdx.x) >> 5;
    int lane = threadIdx.x & 31;
    if (w >= NN) return;
    int beg = g_rowptr[w];
    int end = g_rowptr[w + 1];
    float dv = g_dinv[w];
    float sc = dv * dv;                       // self-loop coefficient
    const float* sr = g_h1 + w * HH;
    bool tail = (lane < HH - 96);

    float a0 = sr[lane] * sc;
    float a1 = sr[32 + lane] * sc;
    float a2 = sr[64 + lane] * sc;
    float a3 = tail ? sr[96 + lane] * sc : 0.f;

    int e = beg;
    for (; e + 4 <= end; e += 4) {
        int s0 = g_csr_src[e],     s1 = g_csr_src[e + 1];
        int s2 = g_csr_src[e + 2], s3 = g_csr_src[e + 3];
        float c0 = g_csr_w[e],     c1 = g_csr_w[e + 1];
        float c2 = g_csr_w[e + 2], c3 = g_csr_w[e + 3];
        const float* r0 = g_h1 + s0 * HH;
        const float* r1 = g_h1 + s1 * HH;
        const float* r2 = g_h1 + s2 * HH;
        const float* r3 = g_h1 + s3 * HH;
        float x00 = r0[lane], x01 = r0[32 + lane], x02 = r0[64 + lane];
        float x10 = r1[lane], x11 = r1[32 + lane], x12 = r1[64 + lane];
        float x20 = r2[lane], x21 = r2[32 + lane], x22 = r2[64 + lane];
        float x30 = r3[lane], x31 = r3[32 + lane], x32 = r3[64 + lane];
        float x03 = tail ? r0[96 + lane] : 0.f;
        float x13 = tail ? r1[96 + lane] : 0.f;
        float x23 = tail ? r2[96 + lane] : 0.f;
        float x33 = tail ? r3[96 + lane] : 0.f;
        a0 += c0 * x00 + c1 * x10 + c2 * x20 + c3 * x30;
        a1 += c0 * x01 + c1 * x11 + c2 * x21 + c3 * x31;
        a2 += c0 * x02 + c1 * x12 + c2 * x22 + c3 * x32;
        a3 += c0 * x03 + c1 * x13 + c2 * x23 + c3 * x33;
    }
    for (; e < end; e++) {
        int s = g_csr_src[e];
        float c = g_csr_w[e];
        const float* r = g_h1 + s * HH;
        a0 += c * r[lane];
        a1 += c * r[32 + lane];
        a2 += c * r[64 + lane];
        if (tail) a3 += c * r[96 + lane];
    }

    float* o = g_h1p + w * HH;
    o[lane] = a0;
    o[32 + lane] = a1;
    o[64 + lane] = a2;
    if (tail) o[96 + lane] = a3;
}

// ===== GEMM2: h2 = leaky(h1p + b1) @ W2  (50000x100 @ 100x16) =====

__global__ __launch_bounds__(256) void k_gemm2(const float* __restrict__ b1,
                                               const float* __restrict__ W2) {
    __shared__ float w2s[HH * CC];
    __shared__ float a1s[16][HH];
    int tid = threadIdx.x;
    int r0  = blockIdx.x * 16;

    for (int i = tid; i < HH * CC; i += 256) w2s[i] = W2[i];
    for (int i = tid; i < 16 * HH; i += 256) {
        int r = i / HH, c = i % HH;
        int gr = r0 + r;
        float v = 0.0f;
        if (gr < NN) {
            v = g_h1p[gr * HH + c] + b1[c];
            v = (v > 0.0f) ? v : 0.01f * v;
        }
        a1s[r][c] = v;
    }
    __syncthreads();

    int r = tid >> 4;
    int c = tid & 15;
    float acc = 0.0f;
#pragma unroll
    for (int k = 0; k < HH; k++) acc += a1s[r][k] * w2s[k * CC + c];
    int gr = r0 + r;
    if (gr < NN) g_h2[gr * CC + c] = acc;
}

// ===== prop2 + bias + log_softmax fused (4 threads per node) =====

__global__ __launch_bounds__(256) void k_prop2_final(const float* __restrict__ b2,
                                                     float* __restrict__ out) {
    int t = blockIdx.x * blockDim.x + threadIdx.x;
    int node = t >> 2;
    int q = t & 3;
    if (node >= NN) return;

    int beg = g_rowptr[node];
    int end = g_rowptr[node + 1];
    float dv = g_dinv[node];
    float sc = dv * dv;

    float4 v = *(const float4*)&g_h2[node * CC + 4 * q];
    float4 acc = make_float4(v.x * sc, v.y * sc, v.z * sc, v.w * sc);

    int e = beg;
    for (; e + 2 <= end; e += 2) {
        int s0 = g_csr_src[e], s1 = g_csr_src[e + 1];
        float c0 = g_csr_w[e], c1 = g_csr_w[e + 1];
        float4 v0 = *(const float4*)&g_h2[s0 * CC + 4 * q];
        float4 v1 = *(const float4*)&g_h2[s1 * CC + 4 * q];
        acc.x += c0 * v0.x + c1 * v1.x;
        acc.y += c0 * v0.y + c1 * v1.y;
        acc.z += c0 * v0.z + c1 * v1.z;
        acc.w += c0 * v0.w + c1 * v1.w;
    }
    for (; e < end; e++) {
        int s = g_csr_src[e];
        float c = g_csr_w[e];
        float4 v0 = *(const float4*)&g_h2[s * CC + 4 * q];
        acc.x += c * v0.x; acc.y += c * v0.y;
        acc.z += c * v0.z; acc.w += c * v0.w;
    }

    float4 bv = ((const float4*)b2)[q];
    acc.x += bv.x; acc.y += bv.y; acc.z += bv.z; acc.w += bv.w;

    // group-of-4 log-softmax over 16 classes
    float m = fmaxf(fmaxf(acc.x, acc.y), fmaxf(acc.z, acc.w));
    m = fmaxf(m, __shfl_xor_sync(0xffffffffu, m, 1, 4));
    m = fmaxf(m, __shfl_xor_sync(0xffffffffu, m, 2, 4));
    float s = expf(acc.x - m) + expf(acc.y - m) + expf(acc.z - m) + expf(acc.w - m);
    s += __shfl_xor_sync(0xffffffffu, s, 1, 4);
    s += __shfl_xor_sync(0xffffffffu, s, 2, 4);
    float ls = m + logf(s);

    float4 o = make_float4(acc.x - ls, acc.y - ls, acc.z - ls, acc.w - ls);
    *(float4*)&out[node * CC + 4 * q] = o;
}

// ================= launcher =================

extern "C" void kernel_launch(void* const* d_in, const int* in_sizes, int n_in,
                              void* d_out, int out_size) {
    const float* x  = (const float*)d_in[0];
    const float* W1 = (const float*)d_in[1];
    const float* b1 = (const float*)d_in[2];
    const float* W2 = (const float*)d_in[3];
    const float* b2 = (const float*)d_in[4];
    const int*   ei = (const int*)d_in[5];
    const int* src = ei;
    const int* dst = ei + EE;
    float* out = (float*)d_out;

    // CSR build
    k_zero<<<(NN + 255) / 256, 256>>>();
    k_count<<<(EE + 255) / 256, 256>>>(dst);
    k_scan1<<<NCHUNK, SCAN_B>>>();
    k_scan2<<<1, 32>>>();
    k_scan3<<<NCHUNK, SCAN_B>>>();
    k_scatter<<<(EE + 255) / 256, 256>>>(src, dst);

    // layer 1
    k_gemm1<<<(NN + 63) / 64, 256>>>(x, W1);
    k_prop1<<<(NN * 32 + 255) / 256, 256>>>();

    // layer 2 + output
    k_gemm2<<<(NN + 15) / 16, 256>>>(b1, W2);
    k_prop2_final<<<(NN * 4 + 255) / 256, 256>>>(b2, out);
}